// round 3
// baseline (speedup 1.0000x reference)
#include <cuda_runtime.h>
#include <math.h>

#define LF 4448   // flux length
#define LP 278    // pooled conv1 length (1112/4)
#define LC2 139   // conv2 output length

// SMEM float offsets
#define OFF_FLUX 0          // 4448 (reused as conv2 output h2)
#define OFF_H1   4448       // 4448 (reused for circuit state / reductions)
#define OFF_W1   8896       // 240
#define OFF_W2   9136       // 3584, layout [(ci*7+t)*32 + c]
#define SMEM_FLOATS 12720   // 50880 bytes

__global__ __launch_bounds__(256)
void aec_kernel(const float* __restrict__ flux,
                const float* __restrict__ scalars,
                const float* __restrict__ c1w,
                const float* __restrict__ bn1g, const float* __restrict__ bn1b,
                const float* __restrict__ c2w,
                const float* __restrict__ bn2g, const float* __restrict__ bn2b,
                const float* __restrict__ pw1, const float* __restrict__ pb1,
                const float* __restrict__ pw2, const float* __restrict__ pb2,
                const float* __restrict__ qw,
                const float* __restrict__ hw1, const float* __restrict__ hb1,
                const float* __restrict__ hbng, const float* __restrict__ hbnb,
                const float* __restrict__ hw2, const float* __restrict__ hb2,
                float* __restrict__ out)
{
    extern __shared__ float sm[];
    float* s_flux = sm + OFF_FLUX;   // later: conv2 output [32][139]
    float* s_h1   = sm + OFF_H1;     // conv1 pooled [16][278]
    float* s_w1   = sm + OFF_W1;
    float* s_w2   = sm + OFF_W2;
    // aliases inside s_h1 region (valid after conv2 consumed h1):
    float* s_re   = s_h1;            // 256
    float* s_im   = s_h1 + 256;      // 256
    float* s_tre  = s_h1 + 512;      // 256 (perm scratch)
    float* s_tim  = s_h1 + 768;      // 256
    float* s_red  = s_h1 + 1024;     // 256 (reductions / probs)
    float* s_feat = s_h1 + 1280;     // 256
    float* s_p1   = s_h1 + 1536;     // 64
    float* s_z    = s_h1 + 1600;     // 8
    float* s_hd   = s_h1 + 1616;     // 32

    const int tid = threadIdx.x;
    const int b   = blockIdx.x;
    const float bnsc = rsqrtf(1.0f + 1e-5f);

    // ---- load flux row + conv weights into SMEM ----
    for (int i = tid; i < LF; i += 256)
        s_flux[i] = flux[(size_t)b * LF + i];
    for (int i = tid; i < 240; i += 256)
        s_w1[i] = c1w[i];                       // [c][t]
    for (int i = tid; i < 3584; i += 256) {     // c2w [c][ci][t] -> [(ci*7+t)*32+c]
        int c = i / 112, r = i % 112, ci = r / 7, t = r % 7;
        s_w2[(ci * 7 + t) * 32 + c] = c2w[i];
    }
    __syncthreads();

    // ---- conv1 + BN + ReLU + MaxPool4 -> s_h1[c][p] ----
    for (int i = tid; i < 16 * LP; i += 256) {
        int c = i & 15, p = i >> 4;
        int base = (p << 4) - 7;
        float xv[27];
        #pragma unroll
        for (int t = 0; t < 27; t++) {
            int ix = base + t;
            xv[t] = (ix >= 0 && ix < LF) ? s_flux[ix] : 0.f;
        }
        float sc = __ldg(&bn1g[c]) * bnsc;
        float bi = __ldg(&bn1b[c]);
        float m = 0.f;  // relu output >= 0
        #pragma unroll
        for (int u = 0; u < 4; u++) {
            float a = 0.f;
            #pragma unroll
            for (int t = 0; t < 15; t++)
                a = fmaf(xv[4 * u + t], s_w1[c * 15 + t], a);
            m = fmaxf(m, fmaf(a, sc, bi));
        }
        s_h1[c * LP + p] = m;
    }
    __syncthreads();

    // ---- conv2 + BN + ReLU -> s_h2 (= s_flux region) [c][p] ----
    float* s_h2 = s_flux;
    for (int i = tid; i < 32 * 35; i += 256) {
        int c = i & 31, g = i >> 5;          // g in [0,35): positions 4g..4g+3
        int base = (g << 3) - 3;
        float a0 = 0.f, a1 = 0.f, a2 = 0.f, a3 = 0.f;
        #pragma unroll
        for (int ci = 0; ci < 16; ci++) {
            float xv[13];
            #pragma unroll
            for (int t = 0; t < 13; t++) {
                int ix = base + t;
                xv[t] = (ix >= 0 && ix < LP) ? s_h1[ci * LP + ix] : 0.f;
            }
            #pragma unroll
            for (int t = 0; t < 7; t++) {
                float w = s_w2[(ci * 7 + t) * 32 + c];
                a0 = fmaf(xv[t],     w, a0);
                a1 = fmaf(xv[t + 2], w, a1);
                a2 = fmaf(xv[t + 4], w, a2);
                a3 = fmaf(xv[t + 6], w, a3);
            }
        }
        float sc = __ldg(&bn2g[c]) * bnsc;
        float bi = __ldg(&bn2b[c]);
        int p0 = g << 2;
        s_h2[c * LC2 + p0] = fmaxf(fmaf(a0, sc, bi), 0.f);
        if (p0 + 1 < LC2) s_h2[c * LC2 + p0 + 1] = fmaxf(fmaf(a1, sc, bi), 0.f);
        if (p0 + 2 < LC2) s_h2[c * LC2 + p0 + 2] = fmaxf(fmaf(a2, sc, bi), 0.f);
        if (p0 + 3 < LC2) s_h2[c * LC2 + p0 + 3] = fmaxf(fmaf(a3, sc, bi), 0.f);
    }
    __syncthreads();

    // ---- adaptive avg pool to 8 -> s_feat[c*8+seg] ----
    {
        int c = tid >> 3, seg = tid & 7;
        int st = (seg * LC2) >> 3;
        int en = ((seg + 1) * LC2 + 7) >> 3;
        float ssum = 0.f;
        for (int t = st; t < en; t++) ssum += s_h2[c * LC2 + t];
        s_feat[c * 8 + seg] = ssum / (float)(en - st);
    }
    __syncthreads();

    // ---- proj1: 256 -> 64, relu (warp per 8 outputs) ----
    {
        int w = tid >> 5, lane = tid & 31;
        for (int oo = 0; oo < 8; oo++) {
            int o = w * 8 + oo;
            float acc = 0.f;
            #pragma unroll
            for (int k = lane; k < 256; k += 32)
                acc = fmaf(s_feat[k], __ldg(&pw1[o * 256 + k]), acc);
            #pragma unroll
            for (int off = 16; off > 0; off >>= 1)
                acc += __shfl_down_sync(0xffffffffu, acc, off);
            if (lane == 0) s_p1[o] = fmaxf(acc + __ldg(&pb1[o]), 0.f);
        }
    }
    __syncthreads();

    // ---- proj2: 64 -> 256, then L2 normalize -> state ----
    float xo = __ldg(&pb2[tid]);
    #pragma unroll
    for (int k = 0; k < 64; k++)
        xo = fmaf(s_p1[k], __ldg(&pw2[tid * 64 + k]), xo);
    s_red[tid] = xo * xo;
    __syncthreads();
    for (int sft = 128; sft > 0; sft >>= 1) {
        if (tid < sft) s_red[tid] += s_red[tid + sft];
        __syncthreads();
    }
    {
        float n = sqrtf(s_red[0]);
        float inv = 1.0f / fmaxf(n, 1e-12f);
        float psi = xo * inv;
        if (n * inv < 1e-8f) psi = 0.0625f;   // uniform 1/sqrt(256)
        s_re[tid] = psi;
        s_im[tid] = 0.f;
    }

    // ---- quantum circuit: 3 layers of (8 Rot gates + CNOT ring) ----
    for (int l = 0; l < 3; l++) {
        for (int q = 0; q < 8; q++) {
            __syncthreads();
            if (tid < 128) {
                const float phi = __ldg(&qw[(l * 8 + q) * 3 + 0]);
                const float th  = __ldg(&qw[(l * 8 + q) * 3 + 1]);
                const float om  = __ldg(&qw[(l * 8 + q) * 3 + 2]);
                float sa, ca, sb, cb, st, ct;
                sincosf(0.5f * (phi + om), &sa, &ca);
                sincosf(0.5f * (phi - om), &sb, &cb);
                sincosf(0.5f * th, &st, &ct);
                int bit = 1 << (7 - q);
                int low = tid & (bit - 1);
                int s0 = ((tid - low) << 1) | low;
                int s1 = s0 | bit;
                float p0r = s_re[s0], p0i = s_im[s0];
                float p1r = s_re[s1], p1i = s_im[s1];
                // U00 = e^{-i(phi+om)/2} c ; U01 = -e^{i(phi-om)/2} s
                // U10 = e^{-i(phi-om)/2} s ; U11 = e^{ i(phi+om)/2} c
                float u00r =  ca * ct, u00i = -sa * ct;
                float u01r = -cb * st, u01i = -sb * st;
                float u10r =  cb * st, u10i = -sb * st;
                float u11r =  ca * ct, u11i =  sa * ct;
                s_re[s0] = u00r * p0r - u00i * p0i + u01r * p1r - u01i * p1i;
                s_im[s0] = u00r * p0i + u00i * p0r + u01r * p1i + u01i * p1r;
                s_re[s1] = u10r * p0r - u10i * p0i + u11r * p1r - u11i * p1i;
                s_im[s1] = u10r * p0i + u10i * p0r + u11r * p1i + u11i * p1r;
            }
        }
        // CNOT ring = one basis permutation: b_k -> prefix-xor(b0..bk) for k>=1,
        // b0 -> b0 ^ prefix-xor(b0..b7)
        __syncthreads();
        {
            int s = tid;
            int bits[8], nb[8];
            #pragma unroll
            for (int k = 0; k < 8; k++) bits[k] = (s >> (7 - k)) & 1;
            int pre = bits[0];
            #pragma unroll
            for (int k = 1; k < 8; k++) { pre ^= bits[k]; nb[k] = pre; }
            nb[0] = bits[0] ^ pre;
            int d = 0;
            #pragma unroll
            for (int k = 0; k < 8; k++) d |= nb[k] << (7 - k);
            s_tre[d] = s_re[s];
            s_tim[d] = s_im[s];
        }
        __syncthreads();
        s_re[tid] = s_tre[tid];
        s_im[tid] = s_tim[tid];
    }
    __syncthreads();

    // ---- <Z_q> expectations (warp w handles qubit w) ----
    s_red[tid] = s_re[tid] * s_re[tid] + s_im[tid] * s_im[tid];
    __syncthreads();
    {
        int w = tid >> 5, lane = tid & 31;
        int bit = 1 << (7 - w);
        float acc = 0.f;
        #pragma unroll
        for (int j = 0; j < 8; j++) {
            int s = lane + 32 * j;
            float pp = s_red[s];
            acc += (s & bit) ? -pp : pp;
        }
        #pragma unroll
        for (int off = 16; off > 0; off >>= 1)
            acc += __shfl_down_sync(0xffffffffu, acc, off);
        if (lane == 0) s_z[w] = acc;
    }
    __syncthreads();

    // ---- head: [z(8), scalars(6)] -> 32 (BN+relu) -> 3 ----
    if (tid < 32) {
        float acc = __ldg(&hb1[tid]);
        #pragma unroll
        for (int k = 0; k < 8; k++)
            acc = fmaf(s_z[k], __ldg(&hw1[tid * 14 + k]), acc);
        #pragma unroll
        for (int k = 0; k < 6; k++)
            acc = fmaf(__ldg(&scalars[(size_t)b * 6 + k]), __ldg(&hw1[tid * 14 + 8 + k]), acc);
        acc = fmaf(acc, __ldg(&hbng[tid]) * bnsc, __ldg(&hbnb[tid]));
        s_hd[tid] = fmaxf(acc, 0.f);
    }
    __syncthreads();
    if (tid < 3) {
        float acc = __ldg(&hb2[tid]);
        #pragma unroll
        for (int j = 0; j < 32; j++)
            acc = fmaf(s_hd[j], __ldg(&hw2[tid * 32 + j]), acc);
        out[(size_t)b * 3 + tid] = acc;
    }
}

extern "C" void kernel_launch(void* const* d_in, const int* in_sizes, int n_in,
                              void* d_out, int out_size)
{
    const float* flux    = (const float*)d_in[0];
    const float* scalars = (const float*)d_in[1];
    const float* c1w     = (const float*)d_in[2];
    const float* bn1g    = (const float*)d_in[3];
    const float* bn1b    = (const float*)d_in[4];
    const float* c2w     = (const float*)d_in[5];
    const float* bn2g    = (const float*)d_in[6];
    const float* bn2b    = (const float*)d_in[7];
    const float* pw1     = (const float*)d_in[8];
    const float* pb1     = (const float*)d_in[9];
    const float* pw2     = (const float*)d_in[10];
    const float* pb2     = (const float*)d_in[11];
    const float* qw      = (const float*)d_in[12];
    const float* hw1     = (const float*)d_in[13];
    const float* hb1     = (const float*)d_in[14];
    const float* hbng    = (const float*)d_in[15];
    const float* hbnb    = (const float*)d_in[16];
    const float* hw2     = (const float*)d_in[17];
    const float* hb2     = (const float*)d_in[18];
    float* out = (float*)d_out;

    int nb = in_sizes[0] / LF;  // batch size
    size_t smem = SMEM_FLOATS * sizeof(float);
    cudaFuncSetAttribute(aec_kernel, cudaFuncAttributeMaxDynamicSharedMemorySize, (int)smem);
    aec_kernel<<<nb, 256, smem>>>(flux, scalars, c1w, bn1g, bn1b, c2w, bn2g, bn2b,
                                  pw1, pb1, pw2, pb2, qw, hw1, hb1, hbng, hbnb,
                                  hw2, hb2, out);
}

// round 6
// speedup vs baseline: 2.3713x; 2.3713x over previous
#include <cuda_runtime.h>
#include <math.h>

#define LF 4448   // flux length
#define LP 278    // pooled conv1 length (1112/4)
#define LC2 139   // conv2 output length

// SMEM float offsets
#define OFF_FLUX 0            // 4448 (reused as conv2 output h2)
#define OFF_H1   4448         // 4448 (reused for circuit state / reductions)
#define OFF_W1   8896         // 240
#define OFF_W2   9136         // 112*33 = 3696, layout [(ci*7+t)*33 + c] (pad 33 kills bank conflicts)
#define SMEM_FLOATS (9136 + 3696)   // 12832 floats = 51328 bytes

// Transposed proj2 weights (k-major) so proj2 LDGs are coalesced.
__device__ float g_pw2t[64 * 256];

__global__ void transpose_pw2_kernel(const float* __restrict__ pw2) {
    int i = blockIdx.x * 256 + threadIdx.x;   // i = o*64 + k
    if (i < 64 * 256) {
        int o = i >> 6, k = i & 63;
        g_pw2t[k * 256 + o] = pw2[i];
    }
}

// conv1 + BN + ReLU + MaxPool4 for 18 consecutive pooled positions, fixed channel.
// Sliding window: 27-wide window advances 16 inputs per pooled position.
template<bool EDGE>
__device__ __forceinline__ void conv1_range(const float* __restrict__ s_flux,
                                            float* __restrict__ s_h1,
                                            const float* w, float sc, float bi,
                                            int c, int p0)
{
    float x[27];
    {
        int base = p0 * 16 - 7;
        #pragma unroll
        for (int t = 0; t < 27; t++) {
            int ix = base + t;
            x[t] = (!EDGE || ((unsigned)ix < LF)) ? s_flux[ix] : 0.f;
        }
    }
    #pragma unroll
    for (int j = 0; j < 18; j++) {
        int pp = p0 + j;
        float m = 0.f;   // relu implied (outputs >= 0 clamp)
        #pragma unroll
        for (int u = 0; u < 4; u++) {
            float a = 0.f;
            #pragma unroll
            for (int t = 0; t < 15; t++)
                a = fmaf(x[4 * u + t], w[t], a);
            m = fmaxf(m, fmaf(a, sc, bi));
        }
        if (!EDGE || pp < LP) s_h1[c * LP + pp] = m;
        if (j < 17) {
            #pragma unroll
            for (int t = 0; t < 11; t++) x[t] = x[t + 16];
            int nbase = (pp + 1) * 16 - 7;
            #pragma unroll
            for (int t = 11; t < 27; t++) {
                int ix = nbase + t;
                x[t] = (!EDGE || ((unsigned)ix < LF)) ? s_flux[ix] : 0.f;
            }
        }
    }
}

// conv2 + BN + ReLU for 18 consecutive output positions, fixed channel.
// Per ci: 7 weights in regs, 7-wide sliding window (stride 2).
template<bool EDGE>
__device__ __forceinline__ void conv2_range(const float* __restrict__ s_h1,
                                            const float* __restrict__ s_w2,
                                            float* __restrict__ s_h2,
                                            float sc, float bi, int c, int p0)
{
    float acc[18];
    #pragma unroll
    for (int j = 0; j < 18; j++) acc[j] = 0.f;

    for (int ci = 0; ci < 16; ci++) {
        float w[7];
        #pragma unroll
        for (int t = 0; t < 7; t++)
            w[t] = s_w2[(ci * 7 + t) * 33 + c];
        const float* row = s_h1 + ci * LP;
        int base = 2 * p0 - 3;
        float x[7];
        #pragma unroll
        for (int t = 0; t < 7; t++) {
            int ix = base + t;
            x[t] = (!EDGE || ((unsigned)ix < LP)) ? row[ix] : 0.f;
        }
        #pragma unroll
        for (int j = 0; j < 18; j++) {
            float a = acc[j];
            #pragma unroll
            for (int t = 0; t < 7; t++)
                a = fmaf(x[t], w[t], a);
            acc[j] = a;
            if (j < 17) {
                #pragma unroll
                for (int t = 0; t < 5; t++) x[t] = x[t + 2];
                int ix0 = base + 2 * (j + 1) + 5;
                x[5] = (!EDGE || ((unsigned)ix0       < LP)) ? row[ix0]     : 0.f;
                x[6] = (!EDGE || ((unsigned)(ix0 + 1) < LP)) ? row[ix0 + 1] : 0.f;
            }
        }
    }
    #pragma unroll
    for (int j = 0; j < 18; j++) {
        int p = p0 + j;
        if (p < LC2) s_h2[c * LC2 + p] = fmaxf(fmaf(acc[j], sc, bi), 0.f);
    }
}

__global__ __launch_bounds__(256)
void aec_kernel(const float* __restrict__ flux,
                const float* __restrict__ scalars,
                const float* __restrict__ c1w,
                const float* __restrict__ bn1g, const float* __restrict__ bn1b,
                const float* __restrict__ c2w,
                const float* __restrict__ bn2g, const float* __restrict__ bn2b,
                const float* __restrict__ pw1, const float* __restrict__ pb1,
                const float* __restrict__ pb2,
                const float* __restrict__ qw,
                const float* __restrict__ hw1, const float* __restrict__ hb1,
                const float* __restrict__ hbng, const float* __restrict__ hbnb,
                const float* __restrict__ hw2, const float* __restrict__ hb2,
                float* __restrict__ out)
{
    extern __shared__ float sm[];
    float* s_flux = sm + OFF_FLUX;   // later: conv2 output h2 [32][139]
    float* s_h1   = sm + OFF_H1;     // conv1 pooled [16][278]
    float* s_w1   = sm + OFF_W1;
    float* s_w2   = sm + OFF_W2;
    // aliases inside s_h1 region (valid after conv2 consumed h1):
    float* s_re   = s_h1;            // 256
    float* s_im   = s_h1 + 256;      // 256
    float* s_tre  = s_h1 + 512;      // 256
    float* s_tim  = s_h1 + 768;      // 256
    float* s_red  = s_h1 + 1024;     // 256
    float* s_feat = s_h1 + 1280;     // 256
    float* s_p1   = s_h1 + 1536;     // 64
    float* s_z    = s_h1 + 1600;     // 8
    float* s_hd   = s_h1 + 1616;     // 32

    const int tid = threadIdx.x;
    const int wid = tid >> 5;
    const int b   = blockIdx.x;
    const float bnsc = rsqrtf(1.0f + 1e-5f);

    // ---- load flux row (float4) + conv weights into SMEM ----
    {
        const float4* f4 = reinterpret_cast<const float4*>(flux + (size_t)b * LF);
        float4* s4 = reinterpret_cast<float4*>(s_flux);
        for (int i = tid; i < LF / 4; i += 256) s4[i] = f4[i];
    }
    for (int i = tid; i < 240; i += 256)
        s_w1[i] = c1w[i];                       // [c][t]
    for (int i = tid; i < 3584; i += 256) {     // c2w [c][ci*7+t] -> [(ci*7+t)*33 + c]
        int c = i / 112, r = i % 112;
        s_w2[r * 33 + c] = c2w[i];
    }
    __syncthreads();

    // ---- conv1 + BN + ReLU + MaxPool4 -> s_h1[c][p] ----
    {
        int c = tid & 15, pr = tid >> 4;        // pr in 0..15, 18 pooled positions each
        float w[15];
        #pragma unroll
        for (int t = 0; t < 15; t++) w[t] = s_w1[c * 15 + t];
        float sc = __ldg(&bn1g[c]) * bnsc;
        float bi = __ldg(&bn1b[c]);
        if (wid == 0 || wid == 7)               // warp-uniform edge branch (pr 0,1,14,15)
            conv1_range<true >(s_flux, s_h1, w, sc, bi, c, pr * 18);
        else
            conv1_range<false>(s_flux, s_h1, w, sc, bi, c, pr * 18);
    }
    __syncthreads();

    // ---- conv2 + BN + ReLU -> s_h2 (= s_flux region) [c][p] ----
    float* s_h2 = s_flux;
    {
        int c = tid & 31, pg = wid;             // pg in 0..7, 18 positions each
        float sc = __ldg(&bn2g[c]) * bnsc;
        float bi = __ldg(&bn2b[c]);
        if (pg == 0 || pg == 7)                 // warp-uniform
            conv2_range<true >(s_h1, s_w2, s_h2, sc, bi, c, pg * 18);
        else
            conv2_range<false>(s_h1, s_w2, s_h2, sc, bi, c, pg * 18);
    }
    __syncthreads();

    // ---- adaptive avg pool to 8 -> s_feat[c*8+seg] ----
    {
        int c = tid >> 3, seg = tid & 7;
        int st = (seg * LC2) >> 3;
        int en = ((seg + 1) * LC2 + 7) >> 3;
        float ssum = 0.f;
        for (int t = st; t < en; t++) ssum += s_h2[c * LC2 + t];
        s_feat[c * 8 + seg] = ssum / (float)(en - st);
    }
    __syncthreads();

    // ---- proj1: 256 -> 64, relu (warp per 8 outputs, coalesced pw1) ----
    {
        int lane = tid & 31;
        for (int oo = 0; oo < 8; oo++) {
            int o = wid * 8 + oo;
            float acc = 0.f;
            #pragma unroll
            for (int k = lane; k < 256; k += 32)
                acc = fmaf(s_feat[k], __ldg(&pw1[o * 256 + k]), acc);
            #pragma unroll
            for (int off = 16; off > 0; off >>= 1)
                acc += __shfl_down_sync(0xffffffffu, acc, off);
            if (lane == 0) s_p1[o] = fmaxf(acc + __ldg(&pb1[o]), 0.f);
        }
    }
    __syncthreads();

    // ---- proj2: 64 -> 256 with transposed weights (coalesced), L2 normalize ----
    float xo = __ldg(&pb2[tid]);
    #pragma unroll 8
    for (int k = 0; k < 64; k++)
        xo = fmaf(s_p1[k], __ldg(&g_pw2t[k * 256 + tid]), xo);
    s_red[tid] = xo * xo;
    __syncthreads();
    for (int sft = 128; sft > 0; sft >>= 1) {
        if (tid < sft) s_red[tid] += s_red[tid + sft];
        __syncthreads();
    }
    {
        float n = sqrtf(s_red[0]);
        float inv = 1.0f / fmaxf(n, 1e-12f);
        float psi = xo * inv;
        if (n * inv < 1e-8f) psi = 0.0625f;   // uniform 1/sqrt(256)
        s_re[tid] = psi;
        s_im[tid] = 0.f;
    }

    // ---- quantum circuit: 3 layers of (8 Rot gates + CNOT ring) ----
    for (int l = 0; l < 3; l++) {
        for (int q = 0; q < 8; q++) {
            __syncthreads();
            if (tid < 128) {
                const float phi = __ldg(&qw[(l * 8 + q) * 3 + 0]);
                const float th  = __ldg(&qw[(l * 8 + q) * 3 + 1]);
                const float om  = __ldg(&qw[(l * 8 + q) * 3 + 2]);
                float sa, ca, sb, cb, st, ct;
                sincosf(0.5f * (phi + om), &sa, &ca);
                sincosf(0.5f * (phi - om), &sb, &cb);
                sincosf(0.5f * th, &st, &ct);
                int bit = 1 << (7 - q);
                int low = tid & (bit - 1);
                int s0 = ((tid - low) << 1) | low;
                int s1 = s0 | bit;
                float p0r = s_re[s0], p0i = s_im[s0];
                float p1r = s_re[s1], p1i = s_im[s1];
                // U00 = e^{-i(phi+om)/2} c ; U01 = -e^{i(phi-om)/2} s
                // U10 = e^{-i(phi-om)/2} s ; U11 = e^{ i(phi+om)/2} c
                float u00r =  ca * ct, u00i = -sa * ct;
                float u01r = -cb * st, u01i = -sb * st;
                float u10r =  cb * st, u10i = -sb * st;
                float u11r =  ca * ct, u11i =  sa * ct;
                s_re[s0] = u00r * p0r - u00i * p0i + u01r * p1r - u01i * p1i;
                s_im[s0] = u00r * p0i + u00i * p0r + u01r * p1i + u01i * p1r;
                s_re[s1] = u10r * p0r - u10i * p0i + u11r * p1r - u11i * p1i;
                s_im[s1] = u10r * p0i + u10i * p0r + u11r * p1i + u11i * p1r;
            }
        }
        // CNOT ring = basis permutation: b_k -> prefix-xor(b0..bk) for k>=1,
        // b0 -> b0 ^ prefix-xor(b0..b7)
        __syncthreads();
        {
            int s = tid;
            int bits[8], nb[8];
            #pragma unroll
            for (int k = 0; k < 8; k++) bits[k] = (s >> (7 - k)) & 1;
            int pre = bits[0];
            #pragma unroll
            for (int k = 1; k < 8; k++) { pre ^= bits[k]; nb[k] = pre; }
            nb[0] = bits[0] ^ pre;
            int d = 0;
            #pragma unroll
            for (int k = 0; k < 8; k++) d |= nb[k] << (7 - k);
            s_tre[d] = s_re[s];
            s_tim[d] = s_im[s];
        }
        __syncthreads();
        s_re[tid] = s_tre[tid];
        s_im[tid] = s_tim[tid];
    }
    __syncthreads();

    // ---- <Z_q> expectations (warp w handles qubit w) ----
    s_red[tid] = s_re[tid] * s_re[tid] + s_im[tid] * s_im[tid];
    __syncthreads();
    {
        int lane = tid & 31;
        int bit = 1 << (7 - wid);
        float acc = 0.f;
        #pragma unroll
        for (int j = 0; j < 8; j++) {
            int s = lane + 32 * j;
            float pp = s_red[s];
            acc += (s & bit) ? -pp : pp;
        }
        #pragma unroll
        for (int off = 16; off > 0; off >>= 1)
            acc += __shfl_down_sync(0xffffffffu, acc, off);
        if (lane == 0) s_z[wid] = acc;
    }
    __syncthreads();

    // ---- head: [z(8), scalars(6)] -> 32 (BN+relu) -> 3 ----
    if (tid < 32) {
        float acc = __ldg(&hb1[tid]);
        #pragma unroll
        for (int k = 0; k < 8; k++)
            acc = fmaf(s_z[k], __ldg(&hw1[tid * 14 + k]), acc);
        #pragma unroll
        for (int k = 0; k < 6; k++)
            acc = fmaf(__ldg(&scalars[(size_t)b * 6 + k]), __ldg(&hw1[tid * 14 + 8 + k]), acc);
        acc = fmaf(acc, __ldg(&hbng[tid]) * bnsc, __ldg(&hbnb[tid]));
        s_hd[tid] = fmaxf(acc, 0.f);
    }
    __syncthreads();
    if (tid < 3) {
        float acc = __ldg(&hb2[tid]);
        #pragma unroll
        for (int j = 0; j < 32; j++)
            acc = fmaf(s_hd[j], __ldg(&hw2[tid * 32 + j]), acc);
        out[(size_t)b * 3 + tid] = acc;
    }
}

extern "C" void kernel_launch(void* const* d_in, const int* in_sizes, int n_in,
                              void* d_out, int out_size)
{
    const float* flux    = (const float*)d_in[0];
    const float* scalars = (const float*)d_in[1];
    const float* c1w     = (const float*)d_in[2];
    const float* bn1g    = (const float*)d_in[3];
    const float* bn1b    = (const float*)d_in[4];
    const float* c2w     = (const float*)d_in[5];
    const float* bn2g    = (const float*)d_in[6];
    const float* bn2b    = (const float*)d_in[7];
    const float* pw1     = (const float*)d_in[8];
    const float* pb1     = (const float*)d_in[9];
    const float* pw2     = (const float*)d_in[10];
    const float* pb2     = (const float*)d_in[11];
    const float* qw      = (const float*)d_in[12];
    const float* hw1     = (const float*)d_in[13];
    const float* hb1     = (const float*)d_in[14];
    const float* hbng    = (const float*)d_in[15];
    const float* hbnb    = (const float*)d_in[16];
    const float* hw2     = (const float*)d_in[17];
    const float* hb2     = (const float*)d_in[18];
    float* out = (float*)d_out;

    int nb = in_sizes[0] / LF;  // batch size
    size_t smem = SMEM_FLOATS * sizeof(float);

    transpose_pw2_kernel<<<64, 256>>>(pw2);

    cudaFuncSetAttribute(aec_kernel, cudaFuncAttributeMaxDynamicSharedMemorySize, (int)smem);
    aec_kernel<<<nb, 256, smem>>>(flux, scalars, c1w, bn1g, bn1b, c2w, bn2g, bn2b,
                                  pw1, pb1, pb2, qw, hw1, hb1, hbng, hbnb,
                                  hw2, hb2, out);
}